// round 10
// baseline (speedup 1.0000x reference)
#include <cuda_runtime.h>
#include <cuda_fp16.h>
#include <math.h>
#include <stdint.h>

// Problem constants
constexpr int B   = 4;
constexpr int S   = 1024;
constexpr int DIM = 2048;
constexpr int H   = 16;
constexpr int HD  = 128;
constexpr int M   = B * S;          // 4096 rows
constexpr float SCALE = 0.08838834764831845f;  // 1/sqrt(128)

// Scratch (allocation-free rule: __device__ globals), fp16.
__device__ __half g_q  [(size_t)M * DIM];
__device__ __half g_k  [(size_t)M * DIM];
__device__ __half g_vt [(size_t)M * DIM];   // transposed: [(b*H+h)*HD+d][s]
__device__ __half g_ctx[(size_t)M * DIM];
__device__ __half c_x  [(size_t)M * DIM];
__device__ __half c_wq [(size_t)DIM * DIM];
__device__ __half c_wk [(size_t)DIM * DIM];
__device__ __half c_wv [(size_t)DIM * DIM];
__device__ __half c_wo [(size_t)DIM * DIM];

__device__ __forceinline__ void mma_f16(float* c, const uint32_t* a, const uint32_t* b) {
    asm volatile(
        "mma.sync.aligned.m16n8k16.row.col.f32.f16.f16.f32 "
        "{%0,%1,%2,%3}, {%4,%5,%6,%7}, {%8,%9}, {%0,%1,%2,%3};"
        : "+f"(c[0]), "+f"(c[1]), "+f"(c[2]), "+f"(c[3])
        : "r"(a[0]), "r"(a[1]), "r"(a[2]), "r"(a[3]), "r"(b[0]), "r"(b[1]));
}

__device__ __forceinline__ void ldsm_x4(uint32_t* r, uint32_t saddr) {
    asm volatile(
        "ldmatrix.sync.aligned.m8n8.x4.shared.b16 {%0,%1,%2,%3}, [%4];"
        : "=r"(r[0]), "=r"(r[1]), "=r"(r[2]), "=r"(r[3]) : "r"(saddr));
}

__device__ __forceinline__ void cp16(uint32_t dst, const void* src) {
    asm volatile("cp.async.cg.shared.global [%0], [%1], 16;" :: "r"(dst), "l"(src));
}

// ---------------------------------------------------------------------------
// Fused elementwise fp32 -> fp16 conversion for all 5 tensors.
// ---------------------------------------------------------------------------
constexpr int NX4 = M * DIM / 4;       // 2097152
constexpr int NW4 = DIM * DIM / 4;     // 1048576
constexpr int NCVT = NX4 + 4 * NW4;    // 6291456

__global__ void cvt5_kernel(const float4* __restrict__ x,
                            const float4* __restrict__ w0, const float4* __restrict__ w1,
                            const float4* __restrict__ w2, const float4* __restrict__ w3,
                            __half2* __restrict__ ox,
                            __half2* __restrict__ o0, __half2* __restrict__ o1,
                            __half2* __restrict__ o2, __half2* __restrict__ o3)
{
    const int i = blockIdx.x * blockDim.x + threadIdx.x;
    if (i >= NCVT) return;
    const float4* src; __half2* dst; int o;
    if (i < NX4) { src = x; dst = ox; o = i; }
    else {
        const int j = i - NX4;
        const int w = j >> 20;            // / NW4
        o = j & (NW4 - 1);
        src = (w == 0) ? w0 : (w == 1) ? w1 : (w == 2) ? w2 : w3;
        dst = (w == 0) ? o0 : (w == 1) ? o1 : (w == 2) ? o2 : o3;
    }
    float4 v = src[o];
    dst[2 * o]     = __floats2half2_rn(v.x, v.y);
    dst[2 * o + 1] = __floats2half2_rn(v.z, v.w);
}

// ---------------------------------------------------------------------------
// fp16 tensor-core GEMM, 3-stage cp.async pipeline, ldmatrix fragment loads.
// 128x128 tile, BK=64, m16n8k16, 8 warps (2x4).
// ---------------------------------------------------------------------------
constexpr int NS_G    = DIM / 64;            // 32 slabs
constexpr int STAGE_G = 2 * 128 * 144;       // bytes per stage (A+B)
constexpr int SMEM_GEMM = 3 * STAGE_G;       // 110592 B

template <int QKV>
__global__ __launch_bounds__(256, 2)
void gemm_f16(const __half* __restrict__ A,
              const __half* __restrict__ W0, const __half* __restrict__ W1,
              const __half* __restrict__ W2,
              const float* __restrict__ b0, const float* __restrict__ b1,
              const float* __restrict__ b2,
              void* __restrict__ C0, void* __restrict__ C1, void* __restrict__ C2,
              const float* __restrict__ cosb, const float* __restrict__ sinb)
{
    constexpr int K = DIM;
    extern __shared__ __half smh[];

    const int z = QKV ? blockIdx.z : 0;
    const __half* W   = (z == 0) ? W0 : (z == 1) ? W1 : W2;
    const float* bias = (z == 0) ? b0 : (z == 1) ? b1 : b2;
    void* C           = (z == 0) ? C0 : (z == 1) ? C1 : C2;
    const bool rope   = QKV && (z < 2);

    const int tid  = threadIdx.x;
    const int warp = tid >> 5, lane = tid & 31;
    const int gid  = lane >> 2, qid = lane & 3;
    const int wm   = warp >> 2, wn = warp & 3;
    const int bm   = blockIdx.y * 128, bn = blockIdx.x * 128;
    const uint32_t sbase = (uint32_t)__cvta_generic_to_shared(smh);

    const int lrow = lane & 15;
    const int lcol = (lane >> 4) * 16;

    float acc[4][4][4];
#pragma unroll
    for (int i = 0; i < 4; i++)
#pragma unroll
        for (int j = 0; j < 4; j++)
#pragma unroll
            for (int c = 0; c < 4; c++) acc[i][j][c] = 0.f;

    auto prefetch = [&](int slab, int st) {
        const int k0 = slab * 64;
        const uint32_t ab = sbase + st * STAGE_G;
        const uint32_t bb = ab + 128 * 144;
#pragma unroll
        for (int i = 0; i < 4; i++) {
            const int c = tid + i * 256;        // 0..1023
            const int row = c >> 3, ch = c & 7; // 128 rows x 8 chunks (16B)
            cp16(ab + row * 144 + ch * 16, A + (size_t)(bm + row) * K + k0 + ch * 8);
            cp16(bb + row * 144 + ch * 16, W + (size_t)(bn + row) * K + k0 + ch * 8);
        }
        asm volatile("cp.async.commit_group;");
    };

    prefetch(0, 0);
    prefetch(1, 1);

    for (int slab = 0; slab < NS_G; slab++) {
        const int st = slab % 3;
        if (slab + 2 < NS_G)
            prefetch(slab + 2, (slab + 2) % 3);
        else
            asm volatile("cp.async.commit_group;");   // keep group count aligned
        asm volatile("cp.async.wait_group 2;" ::: "memory");
        __syncthreads();

        const uint32_t ab = sbase + st * STAGE_G;
        const uint32_t bb = ab + 128 * 144;
#pragma unroll
        for (int ks = 0; ks < 4; ks++) {
            const int kcb = ks * 32 + lcol;     // col offset in bytes
            uint32_t a[4][4], b[4][2];
#pragma unroll
            for (int mf = 0; mf < 4; mf++) {
                const int r = wm * 64 + mf * 16 + lrow;
                ldsm_x4(a[mf], ab + r * 144 + kcb);
            }
#pragma unroll
            for (int np = 0; np < 2; np++) {
                uint32_t t[4];
                const int r = wn * 32 + np * 16 + lrow;
                ldsm_x4(t, bb + r * 144 + kcb);
                b[2 * np    ][0] = t[0]; b[2 * np    ][1] = t[2];
                b[2 * np + 1][0] = t[1]; b[2 * np + 1][1] = t[3];
            }
#pragma unroll
            for (int mf = 0; mf < 4; mf++)
#pragma unroll
                for (int nf = 0; nf < 4; nf++)
                    mma_f16(acc[mf][nf], a[mf], b[nf]);
        }
        __syncthreads();
    }

    // Epilogue: bias (+ RoPE on adjacent column pairs).
#pragma unroll
    for (int mf = 0; mf < 4; mf++) {
#pragma unroll
        for (int hf = 0; hf < 2; hf++) {
            const int row = bm + wm * 64 + mf * 16 + gid + hf * 8;
            const int s   = row & (S - 1);
#pragma unroll
            for (int nf = 0; nf < 4; nf++) {
                const int col = bn + wn * 32 + nf * 8 + 2 * qid;
                float v0 = acc[mf][nf][hf * 2 + 0] + bias[col];
                float v1 = acc[mf][nf][hf * 2 + 1] + bias[col + 1];
                if (rope) {
                    const int f = (col & (HD - 1)) >> 1;
                    const float cc = cosb[s * 64 + f], ss = sinb[s * 64 + f];
                    const float o0 = v0 * cc - v1 * ss;
                    const float o1 = v0 * ss + v1 * cc;
                    v0 = o0; v1 = o1;
                }
                if (QKV) {
                    if (z == 2) {
                        const int bb2 = row >> 10, sp = row & 1023;
                        const int hh = col >> 7, dd = col & 127;
                        __half* vt = (__half*)C;
                        vt[((size_t)((bb2 * H + hh) * HD + dd)) * S + sp] =
                            __float2half(v0);
                        vt[((size_t)((bb2 * H + hh) * HD + dd + 1)) * S + sp] =
                            __float2half(v1);
                    } else {
                        *(__half2*)((__half*)C + (size_t)row * DIM + col) =
                            __floats2half2_rn(v0, v1);
                    }
                } else {
                    *(float2*)((float*)C + (size_t)row * DIM + col) =
                        make_float2(v0, v1);
                }
            }
        }
    }
}

// ---------------------------------------------------------------------------
// fp16 tensor-core flash attention, 3-stage K/V pipeline, ldmatrix loads.
// Block = (b, h, 128 q); 8 warps x 16 q; 64-key tiles.
// S^T = K Q^T, then O^T = V^T P (V pre-transposed in gmem).
// ---------------------------------------------------------------------------
constexpr int QROW = 136, KROW = 136, VROW = 72, PROW = 72;   // halfs per row
constexpr int SMEM_ATTN =
    (128 * QROW + 3 * 64 * KROW + 3 * 128 * VROW + 8 * 16 * PROW) * 2;  // 160768

__global__ __launch_bounds__(256)
void attn_kernel()
{
    extern __shared__ __half smh[];
    __half* Qs  = smh;                       // [128 q][136 d]
    __half* Ks0 = Qs + 128 * QROW;           // 3 x [64 k][136 d]
    __half* Vt0 = Ks0 + 3 * 64 * KROW;       // 3 x [128 d][72 k]
    __half* Pb  = Vt0 + 3 * 128 * VROW;      // 8 x [16 q][72 k]

    const int tid  = threadIdx.x;
    const int warp = tid >> 5, lane = tid & 31;
    const int gid  = lane >> 2, qid = lane & 3;
    const int qb   = blockIdx.x * 128;
    const int h    = blockIdx.y;
    const int b    = blockIdx.z;
    const size_t baseq = (size_t)b * S * DIM + (size_t)h * HD;
    const size_t basev = (size_t)((b * H + h) * HD) * S;
    const int q0 = warp * 16;
    __half* Pw = Pb + warp * 16 * PROW;

    const int lrow = lane & 15;
    const int lcol = (lane >> 4) * 16;       // bytes

    const uint32_t qs_b = (uint32_t)__cvta_generic_to_shared(Qs);
    const uint32_t pw_b = (uint32_t)__cvta_generic_to_shared(Pw);

    auto cp_tile = [&](int kb, int buf) {
        const uint32_t kd = (uint32_t)__cvta_generic_to_shared(Ks0 + buf * 64 * KROW);
        const uint32_t vd = (uint32_t)__cvta_generic_to_shared(Vt0 + buf * 128 * VROW);
#pragma unroll
        for (int i = 0; i < 4; i++) {          // K: 64 rows x 16 chunks
            const int c = tid + i * 256;
            const int row = c >> 4, ch = c & 15;
            cp16(kd + row * 272 + ch * 16,
                 g_k + baseq + (size_t)(kb + row) * DIM + ch * 8);
        }
#pragma unroll
        for (int i = 0; i < 4; i++) {          // V^T: 128 rows x 8 chunks
            const int c = tid + i * 256;
            const int row = c >> 3, ch = c & 7;
            cp16(vd + row * 144 + ch * 16,
                 g_vt + basev + (size_t)row * S + kb + ch * 8);
        }
        asm volatile("cp.async.commit_group;");
    };

    const int nt = qb / 64 + 2;
    cp_tile(0, 0);
    cp_tile(64, 1);
    for (int i = tid; i < 2048; i += 256) {    // Q: 128 rows x 16 chunks
        const int row = i >> 4, ch = i & 15;
        *(uint4*)(Qs + row * QROW + ch * 8) =
            *(const uint4*)(g_q + baseq + (size_t)(qb + row) * DIM + ch * 8);
    }

    float oacc[8][2][4];
#pragma unroll
    for (int i = 0; i < 8; i++)
#pragma unroll
        for (int j = 0; j < 2; j++)
#pragma unroll
            for (int c = 0; c < 4; c++) oacc[i][j][c] = 0.f;
    float rm[4] = {-1e30f, -1e30f, -1e30f, -1e30f};
    float rl[4] = {0.f, 0.f, 0.f, 0.f};

    for (int t = 0; t < nt; t++) {
        const int kb = t * 64;
        const int buf = t % 3;
        if (t + 2 < nt)
            cp_tile(kb + 128, (t + 2) % 3);
        else
            asm volatile("cp.async.commit_group;");
        asm volatile("cp.async.wait_group 2;" ::: "memory");
        __syncthreads();

        const uint32_t kd = (uint32_t)__cvta_generic_to_shared(Ks0 + buf * 64 * KROW);
        const uint32_t vd = (uint32_t)__cvta_generic_to_shared(Vt0 + buf * 128 * VROW);

        if (kb <= qb + q0 + 15) {
            // S^T = K @ Q^T
            float sacc[4][2][4];
#pragma unroll
            for (int i = 0; i < 4; i++)
#pragma unroll
                for (int j = 0; j < 2; j++)
#pragma unroll
                    for (int c = 0; c < 4; c++) sacc[i][j][c] = 0.f;

#pragma unroll
            for (int ks = 0; ks < 8; ks++) {   // 8 k-steps of 16
                const int kcb = ks * 32 + lcol;
                uint32_t a[4][4], bq[2][2];
#pragma unroll
                for (int mf = 0; mf < 4; mf++)
                    ldsm_x4(a[mf], kd + (mf * 16 + lrow) * 272 + kcb);
                {
                    uint32_t tq[4];
                    ldsm_x4(tq, qs_b + (q0 + lrow) * 272 + kcb);
                    bq[0][0] = tq[0]; bq[0][1] = tq[2];
                    bq[1][0] = tq[1]; bq[1][1] = tq[3];
                }
#pragma unroll
                for (int mf = 0; mf < 4; mf++)
#pragma unroll
                    for (int nf = 0; nf < 2; nf++)
                        mma_f16(sacc[mf][nf], a[mf], bq[nf]);
            }

            const bool diag = (kb + 63 > qb + q0);
            float mloc[4] = {-1e30f, -1e30f, -1e30f, -1e30f};
#pragma unroll
            for (int mf = 0; mf < 4; mf++)
#pragma unroll
                for (int nf = 0; nf < 2; nf++)
#pragma unroll
                    for (int ci = 0; ci < 4; ci++) {
                        float sv = sacc[mf][nf][ci] * SCALE;
                        if (diag) {
                            const int key = kb + mf * 16 + gid + ((ci >> 1) << 3);
                            const int q   = qb + q0 + nf * 8 + 2 * qid + (ci & 1);
                            if (key > q) sv = -1e30f;
                        }
                        sacc[mf][nf][ci] = sv;
                        const int j = nf * 2 + (ci & 1);
                        mloc[j] = fmaxf(mloc[j], sv);
                    }
#pragma unroll
            for (int j = 0; j < 4; j++) {
                mloc[j] = fmaxf(mloc[j], __shfl_xor_sync(0xffffffffu, mloc[j], 4));
                mloc[j] = fmaxf(mloc[j], __shfl_xor_sync(0xffffffffu, mloc[j], 8));
                mloc[j] = fmaxf(mloc[j], __shfl_xor_sync(0xffffffffu, mloc[j], 16));
            }
            float corr[4];
#pragma unroll
            for (int j = 0; j < 4; j++) {
                const float newm = fmaxf(rm[j], mloc[j]);
                corr[j] = __expf(rm[j] - newm);
                rm[j] = newm;
            }
            float psum[4] = {0.f, 0.f, 0.f, 0.f};
#pragma unroll
            for (int mf = 0; mf < 4; mf++)
#pragma unroll
                for (int nf = 0; nf < 2; nf++)
#pragma unroll
                    for (int ci = 0; ci < 4; ci++) {
                        const int j = nf * 2 + (ci & 1);
                        const float p = __expf(sacc[mf][nf][ci] - rm[j]);
                        psum[j] += p;
                        const int key = mf * 16 + gid + ((ci >> 1) << 3);
                        const int qq  = nf * 8 + 2 * qid + (ci & 1);
                        Pw[qq * PROW + key] = __float2half(p);
                    }
#pragma unroll
            for (int j = 0; j < 4; j++) {
                psum[j] += __shfl_xor_sync(0xffffffffu, psum[j], 4);
                psum[j] += __shfl_xor_sync(0xffffffffu, psum[j], 8);
                psum[j] += __shfl_xor_sync(0xffffffffu, psum[j], 16);
                rl[j] = rl[j] * corr[j] + psum[j];
            }
#pragma unroll
            for (int mfo = 0; mfo < 8; mfo++)
#pragma unroll
                for (int nf = 0; nf < 2; nf++)
#pragma unroll
                    for (int ci = 0; ci < 4; ci++)
                        oacc[mfo][nf][ci] *= corr[nf * 2 + (ci & 1)];

            __syncwarp();

            // O^T += V^T @ P
#pragma unroll
            for (int ko = 0; ko < 4; ko++) {
                const int kcb = ko * 32 + lcol;
                uint32_t bp[2][2];
                {
                    uint32_t tp[4];
                    ldsm_x4(tp, pw_b + lrow * 144 + kcb);
                    bp[0][0] = tp[0]; bp[0][1] = tp[2];
                    bp[1][0] = tp[1]; bp[1][1] = tp[3];
                }
#pragma unroll
                for (int mfo = 0; mfo < 8; mfo++) {
                    uint32_t a[4];
                    ldsm_x4(a, vd + (mfo * 16 + lrow) * 144 + kcb);
#pragma unroll
                    for (int nf = 0; nf < 2; nf++)
                        mma_f16(oacc[mfo][nf], a, bp[nf]);
                }
            }
        }
        __syncthreads();
    }

    float inv[4];
#pragma unroll
    for (int j = 0; j < 4; j++) inv[j] = 1.f / rl[j];
#pragma unroll
    for (int mfo = 0; mfo < 8; mfo++)
#pragma unroll
        for (int nf = 0; nf < 2; nf++)
#pragma unroll
            for (int ci = 0; ci < 4; ci++) {
                const int d = mfo * 16 + gid + ((ci >> 1) << 3);
                const int q = qb + q0 + nf * 8 + 2 * qid + (ci & 1);
                g_ctx[baseq + (size_t)q * DIM + d] =
                    __float2half(oacc[mfo][nf][ci] * inv[nf * 2 + (ci & 1)]);
            }
}

// ---------------------------------------------------------------------------
// Launch
// ---------------------------------------------------------------------------
extern "C" void kernel_launch(void* const* d_in, const int* in_sizes, int n_in,
                              void* d_out, int out_size)
{
    const float* x    = (const float*)d_in[0];
    const float* cosb = (const float*)d_in[2];
    const float* sinb = (const float*)d_in[3];
    const float* wq   = (const float*)d_in[5];
    const float* bq   = (const float*)d_in[6];
    const float* wk   = (const float*)d_in[7];
    const float* bk   = (const float*)d_in[8];
    const float* wv   = (const float*)d_in[9];
    const float* bv   = (const float*)d_in[10];
    const float* wo   = (const float*)d_in[11];
    const float* bo   = (const float*)d_in[12];
    float* out = (float*)d_out;

    __half *q, *k, *vt, *ctx, *cx, *cwq, *cwk, *cwv, *cwo;
    cudaGetSymbolAddress((void**)&q,   g_q);
    cudaGetSymbolAddress((void**)&k,   g_k);
    cudaGetSymbolAddress((void**)&vt,  g_vt);
    cudaGetSymbolAddress((void**)&ctx, g_ctx);
    cudaGetSymbolAddress((void**)&cx,  c_x);
    cudaGetSymbolAddress((void**)&cwq, c_wq);
    cudaGetSymbolAddress((void**)&cwk, c_wk);
    cudaGetSymbolAddress((void**)&cwv, c_wv);
    cudaGetSymbolAddress((void**)&cwo, c_wo);

    cudaFuncSetAttribute(attn_kernel,
                         cudaFuncAttributeMaxDynamicSharedMemorySize, SMEM_ATTN);
    cudaFuncSetAttribute(gemm_f16<1>,
                         cudaFuncAttributeMaxDynamicSharedMemorySize, SMEM_GEMM);
    cudaFuncSetAttribute(gemm_f16<0>,
                         cudaFuncAttributeMaxDynamicSharedMemorySize, SMEM_GEMM);

    // fp32 -> fp16 pre-conversion (fused, one launch)
    cvt5_kernel<<<(NCVT + 255) / 256, 256>>>(
        (const float4*)x, (const float4*)wq, (const float4*)wk,
        (const float4*)wv, (const float4*)wo,
        (__half2*)cx, (__half2*)cwq, (__half2*)cwk, (__half2*)cwv, (__half2*)cwo);

    // Fused QKV projections (+bias, +RoPE for q/k; v stored transposed)
    dim3 gqkv(DIM / 128, M / 128, 3);   // (16, 32, 3)
    gemm_f16<1><<<gqkv, 256, SMEM_GEMM>>>(cx, cwq, cwk, cwv, bq, bk, bv,
                                          q, k, vt, cosb, sinb);

    dim3 adim(S / 128, H, B);           // (8, 16, 4)
    attn_kernel<<<adim, 256, SMEM_ATTN>>>();

    dim3 gdim(DIM / 128, M / 128, 1);
    gemm_f16<0><<<gdim, 256, SMEM_GEMM>>>(ctx, cwo, cwo, cwo, bo, bo, bo,
                                          out, out, out, cosb, sinb);
}

// round 11
// speedup vs baseline: 1.0211x; 1.0211x over previous
#include <cuda_runtime.h>
#include <cuda_fp16.h>
#include <math.h>
#include <stdint.h>

// Problem constants
constexpr int B   = 4;
constexpr int S   = 1024;
constexpr int DIM = 2048;
constexpr int H   = 16;
constexpr int HD  = 128;
constexpr int M   = B * S;          // 4096 rows
constexpr float SCALE = 0.08838834764831845f;  // 1/sqrt(128)

// Scratch (allocation-free rule: __device__ globals), fp16.
__device__ __half g_q  [(size_t)M * DIM];
__device__ __half g_k  [(size_t)M * DIM];
__device__ __half g_vt [(size_t)M * DIM];   // transposed: [(b*H+h)*HD+d][s]
__device__ __half g_ctx[(size_t)M * DIM];
__device__ __half c_x  [(size_t)M * DIM];
__device__ __half c_wq [(size_t)DIM * DIM];
__device__ __half c_wk [(size_t)DIM * DIM];
__device__ __half c_wv [(size_t)DIM * DIM];
__device__ __half c_wo [(size_t)DIM * DIM];

__device__ __forceinline__ void mma_f16(float* c, const uint32_t* a, const uint32_t* b) {
    asm volatile(
        "mma.sync.aligned.m16n8k16.row.col.f32.f16.f16.f32 "
        "{%0,%1,%2,%3}, {%4,%5,%6,%7}, {%8,%9}, {%0,%1,%2,%3};"
        : "+f"(c[0]), "+f"(c[1]), "+f"(c[2]), "+f"(c[3])
        : "r"(a[0]), "r"(a[1]), "r"(a[2]), "r"(a[3]), "r"(b[0]), "r"(b[1]));
}

__device__ __forceinline__ void ldsm_x4(uint32_t* r, uint32_t saddr) {
    asm volatile(
        "ldmatrix.sync.aligned.m8n8.x4.shared.b16 {%0,%1,%2,%3}, [%4];"
        : "=r"(r[0]), "=r"(r[1]), "=r"(r[2]), "=r"(r[3]) : "r"(saddr));
}

__device__ __forceinline__ void cp16(uint32_t dst, const void* src) {
    asm volatile("cp.async.cg.shared.global [%0], [%1], 16;" :: "r"(dst), "l"(src));
}

// ---------------------------------------------------------------------------
// Fused elementwise fp32 -> fp16 conversion for all 5 tensors.
// ---------------------------------------------------------------------------
constexpr int NX4 = M * DIM / 4;       // 2097152
constexpr int NW4 = DIM * DIM / 4;     // 1048576
constexpr int NCVT = NX4 + 4 * NW4;    // 6291456

__global__ void cvt5_kernel(const float4* __restrict__ x,
                            const float4* __restrict__ w0, const float4* __restrict__ w1,
                            const float4* __restrict__ w2, const float4* __restrict__ w3,
                            __half2* __restrict__ ox,
                            __half2* __restrict__ o0, __half2* __restrict__ o1,
                            __half2* __restrict__ o2, __half2* __restrict__ o3)
{
    const int i = blockIdx.x * blockDim.x + threadIdx.x;
    if (i >= NCVT) return;
    const float4* src; __half2* dst; int o;
    if (i < NX4) { src = x; dst = ox; o = i; }
    else {
        const int j = i - NX4;
        const int w = j >> 20;            // / NW4
        o = j & (NW4 - 1);
        src = (w == 0) ? w0 : (w == 1) ? w1 : (w == 2) ? w2 : w3;
        dst = (w == 0) ? o0 : (w == 1) ? o1 : (w == 2) ? o2 : o3;
    }
    float4 v = src[o];
    dst[2 * o]     = __floats2half2_rn(v.x, v.y);
    dst[2 * o + 1] = __floats2half2_rn(v.z, v.w);
}

// ---------------------------------------------------------------------------
// fp16 tensor-core GEMM, 3-stage cp.async pipeline, ONE barrier per slab.
// Loop order: wait -> sync -> prefetch(s+2) -> compute(s).
// 128x128 tile, BK=64, m16n8k16, 8 warps (2x4).
// ---------------------------------------------------------------------------
constexpr int NS_G    = DIM / 64;            // 32 slabs
constexpr int STAGE_G = 2 * 128 * 144;       // bytes per stage (A+B)
constexpr int SMEM_GEMM = 3 * STAGE_G;       // 110592 B

template <int QKV>
__global__ __launch_bounds__(256, 2)
void gemm_f16(const __half* __restrict__ A,
              const __half* __restrict__ W0, const __half* __restrict__ W1,
              const __half* __restrict__ W2,
              const float* __restrict__ b0, const float* __restrict__ b1,
              const float* __restrict__ b2,
              void* __restrict__ C0, void* __restrict__ C1, void* __restrict__ C2,
              const float* __restrict__ cosb, const float* __restrict__ sinb)
{
    constexpr int K = DIM;
    extern __shared__ __half smh[];

    const int z = QKV ? blockIdx.z : 0;
    const __half* W   = (z == 0) ? W0 : (z == 1) ? W1 : W2;
    const float* bias = (z == 0) ? b0 : (z == 1) ? b1 : b2;
    void* C           = (z == 0) ? C0 : (z == 1) ? C1 : C2;
    const bool rope   = QKV && (z < 2);

    const int tid  = threadIdx.x;
    const int warp = tid >> 5, lane = tid & 31;
    const int gid  = lane >> 2, qid = lane & 3;
    const int wm   = warp >> 2, wn = warp & 3;
    const int bm   = blockIdx.y * 128, bn = blockIdx.x * 128;
    const uint32_t sbase = (uint32_t)__cvta_generic_to_shared(smh);

    const int lrow = lane & 15;
    const int lcol = (lane >> 4) * 16;

    float acc[4][4][4];
#pragma unroll
    for (int i = 0; i < 4; i++)
#pragma unroll
        for (int j = 0; j < 4; j++)
#pragma unroll
            for (int c = 0; c < 4; c++) acc[i][j][c] = 0.f;

    auto prefetch = [&](int slab, int st) {
        const int k0 = slab * 64;
        const uint32_t ab = sbase + st * STAGE_G;
        const uint32_t bb = ab + 128 * 144;
#pragma unroll
        for (int i = 0; i < 4; i++) {
            const int c = tid + i * 256;        // 0..1023
            const int row = c >> 3, ch = c & 7; // 128 rows x 8 chunks (16B)
            cp16(ab + row * 144 + ch * 16, A + (size_t)(bm + row) * K + k0 + ch * 8);
            cp16(bb + row * 144 + ch * 16, W + (size_t)(bn + row) * K + k0 + ch * 8);
        }
        asm volatile("cp.async.commit_group;");
    };

    prefetch(0, 0);
    prefetch(1, 1);

    for (int slab = 0; slab < NS_G; slab++) {
        const int st = slab % 3;
        // Group for this slab is done when <=1 newer group outstanding
        // (last slab: nothing newer in flight -> wait all).
        if (slab + 1 < NS_G)
            asm volatile("cp.async.wait_group 1;" ::: "memory");
        else
            asm volatile("cp.async.wait_group 0;" ::: "memory");
        __syncthreads();   // single barrier: readers of stage (s+2)%3 done too

        if (slab + 2 < NS_G)
            prefetch(slab + 2, (slab + 2) % 3);

        const uint32_t ab = sbase + st * STAGE_G;
        const uint32_t bb = ab + 128 * 144;
#pragma unroll
        for (int ks = 0; ks < 4; ks++) {
            const int kcb = ks * 32 + lcol;     // col offset in bytes
            uint32_t a[4][4], b[4][2];
#pragma unroll
            for (int mf = 0; mf < 4; mf++) {
                const int r = wm * 64 + mf * 16 + lrow;
                ldsm_x4(a[mf], ab + r * 144 + kcb);
            }
#pragma unroll
            for (int np = 0; np < 2; np++) {
                uint32_t t[4];
                const int r = wn * 32 + np * 16 + lrow;
                ldsm_x4(t, bb + r * 144 + kcb);
                b[2 * np    ][0] = t[0]; b[2 * np    ][1] = t[2];
                b[2 * np + 1][0] = t[1]; b[2 * np + 1][1] = t[3];
            }
#pragma unroll
            for (int mf = 0; mf < 4; mf++)
#pragma unroll
                for (int nf = 0; nf < 4; nf++)
                    mma_f16(acc[mf][nf], a[mf], b[nf]);
        }
    }

    // Epilogue: bias (+ RoPE on adjacent column pairs).
#pragma unroll
    for (int mf = 0; mf < 4; mf++) {
#pragma unroll
        for (int hf = 0; hf < 2; hf++) {
            const int row = bm + wm * 64 + mf * 16 + gid + hf * 8;
            const int s   = row & (S - 1);
#pragma unroll
            for (int nf = 0; nf < 4; nf++) {
                const int col = bn + wn * 32 + nf * 8 + 2 * qid;
                float v0 = acc[mf][nf][hf * 2 + 0] + bias[col];
                float v1 = acc[mf][nf][hf * 2 + 1] + bias[col + 1];
                if (rope) {
                    const int f = (col & (HD - 1)) >> 1;
                    const float cc = cosb[s * 64 + f], ss = sinb[s * 64 + f];
                    const float o0 = v0 * cc - v1 * ss;
                    const float o1 = v0 * ss + v1 * cc;
                    v0 = o0; v1 = o1;
                }
                if (QKV) {
                    if (z == 2) {
                        const int bb2 = row >> 10, sp = row & 1023;
                        const int hh = col >> 7, dd = col & 127;
                        __half* vt = (__half*)C;
                        vt[((size_t)((bb2 * H + hh) * HD + dd)) * S + sp] =
                            __float2half(v0);
                        vt[((size_t)((bb2 * H + hh) * HD + dd + 1)) * S + sp] =
                            __float2half(v1);
                    } else {
                        *(__half2*)((__half*)C + (size_t)row * DIM + col) =
                            __floats2half2_rn(v0, v1);
                    }
                } else {
                    *(float2*)((float*)C + (size_t)row * DIM + col) =
                        make_float2(v0, v1);
                }
            }
        }
    }
}

// ---------------------------------------------------------------------------
// fp16 tensor-core flash attention, 3-stage K/V pipeline, ONE barrier/tile.
// Block = (b, h, 128 q); 8 warps x 16 q; 64-key tiles.
// S^T = K Q^T, then O^T = V^T P (V pre-transposed in gmem).
// ---------------------------------------------------------------------------
constexpr int QROW = 136, KROW = 136, VROW = 72, PROW = 72;   // halfs per row
constexpr int SMEM_ATTN =
    (128 * QROW + 3 * 64 * KROW + 3 * 128 * VROW + 8 * 16 * PROW) * 2;  // 160768

__global__ __launch_bounds__(256)
void attn_kernel()
{
    extern __shared__ __half smh[];
    __half* Qs  = smh;                       // [128 q][136 d]
    __half* Ks0 = Qs + 128 * QROW;           // 3 x [64 k][136 d]
    __half* Vt0 = Ks0 + 3 * 64 * KROW;       // 3 x [128 d][72 k]
    __half* Pb  = Vt0 + 3 * 128 * VROW;      // 8 x [16 q][72 k]

    const int tid  = threadIdx.x;
    const int warp = tid >> 5, lane = tid & 31;
    const int gid  = lane >> 2, qid = lane & 3;
    const int qb   = blockIdx.x * 128;
    const int h    = blockIdx.y;
    const int b    = blockIdx.z;
    const size_t baseq = (size_t)b * S * DIM + (size_t)h * HD;
    const size_t basev = (size_t)((b * H + h) * HD) * S;
    const int q0 = warp * 16;
    __half* Pw = Pb + warp * 16 * PROW;

    const int lrow = lane & 15;
    const int lcol = (lane >> 4) * 16;       // bytes

    const uint32_t qs_b = (uint32_t)__cvta_generic_to_shared(Qs);
    const uint32_t pw_b = (uint32_t)__cvta_generic_to_shared(Pw);

    auto cp_tile = [&](int kb, int buf) {
        const uint32_t kd = (uint32_t)__cvta_generic_to_shared(Ks0 + buf * 64 * KROW);
        const uint32_t vd = (uint32_t)__cvta_generic_to_shared(Vt0 + buf * 128 * VROW);
#pragma unroll
        for (int i = 0; i < 4; i++) {          // K: 64 rows x 16 chunks
            const int c = tid + i * 256;
            const int row = c >> 4, ch = c & 15;
            cp16(kd + row * 272 + ch * 16,
                 g_k + baseq + (size_t)(kb + row) * DIM + ch * 8);
        }
#pragma unroll
        for (int i = 0; i < 4; i++) {          // V^T: 128 rows x 8 chunks
            const int c = tid + i * 256;
            const int row = c >> 3, ch = c & 7;
            cp16(vd + row * 144 + ch * 16,
                 g_vt + basev + (size_t)row * S + kb + ch * 8);
        }
        asm volatile("cp.async.commit_group;");
    };

    const int nt = qb / 64 + 2;
    cp_tile(0, 0);
    cp_tile(64, 1);
    for (int i = tid; i < 2048; i += 256) {    // Q: 128 rows x 16 chunks
        const int row = i >> 4, ch = i & 15;
        *(uint4*)(Qs + row * QROW + ch * 8) =
            *(const uint4*)(g_q + baseq + (size_t)(qb + row) * DIM + ch * 8);
    }

    float oacc[8][2][4];
#pragma unroll
    for (int i = 0; i < 8; i++)
#pragma unroll
        for (int j = 0; j < 2; j++)
#pragma unroll
            for (int c = 0; c < 4; c++) oacc[i][j][c] = 0.f;
    float rm[4] = {-1e30f, -1e30f, -1e30f, -1e30f};
    float rl[4] = {0.f, 0.f, 0.f, 0.f};

    for (int t = 0; t < nt; t++) {
        const int kb = t * 64;
        const int buf = t % 3;
        if (t + 1 < nt)
            asm volatile("cp.async.wait_group 1;" ::: "memory");
        else
            asm volatile("cp.async.wait_group 0;" ::: "memory");
        __syncthreads();   // single barrier per tile

        if (t + 2 < nt)
            cp_tile(kb + 128, (t + 2) % 3);

        const uint32_t kd = (uint32_t)__cvta_generic_to_shared(Ks0 + buf * 64 * KROW);
        const uint32_t vd = (uint32_t)__cvta_generic_to_shared(Vt0 + buf * 128 * VROW);

        if (kb <= qb + q0 + 15) {
            // S^T = K @ Q^T
            float sacc[4][2][4];
#pragma unroll
            for (int i = 0; i < 4; i++)
#pragma unroll
                for (int j = 0; j < 2; j++)
#pragma unroll
                    for (int c = 0; c < 4; c++) sacc[i][j][c] = 0.f;

#pragma unroll
            for (int ks = 0; ks < 8; ks++) {   // 8 k-steps of 16
                const int kcb = ks * 32 + lcol;
                uint32_t a[4][4], bq[2][2];
#pragma unroll
                for (int mf = 0; mf < 4; mf++)
                    ldsm_x4(a[mf], kd + (mf * 16 + lrow) * 272 + kcb);
                {
                    uint32_t tq[4];
                    ldsm_x4(tq, qs_b + (q0 + lrow) * 272 + kcb);
                    bq[0][0] = tq[0]; bq[0][1] = tq[2];
                    bq[1][0] = tq[1]; bq[1][1] = tq[3];
                }
#pragma unroll
                for (int mf = 0; mf < 4; mf++)
#pragma unroll
                    for (int nf = 0; nf < 2; nf++)
                        mma_f16(sacc[mf][nf], a[mf], bq[nf]);
            }

            const bool diag = (kb + 63 > qb + q0);
            float mloc[4] = {-1e30f, -1e30f, -1e30f, -1e30f};
#pragma unroll
            for (int mf = 0; mf < 4; mf++)
#pragma unroll
                for (int nf = 0; nf < 2; nf++)
#pragma unroll
                    for (int ci = 0; ci < 4; ci++) {
                        float sv = sacc[mf][nf][ci] * SCALE;
                        if (diag) {
                            const int key = kb + mf * 16 + gid + ((ci >> 1) << 3);
                            const int q   = qb + q0 + nf * 8 + 2 * qid + (ci & 1);
                            if (key > q) sv = -1e30f;
                        }
                        sacc[mf][nf][ci] = sv;
                        const int j = nf * 2 + (ci & 1);
                        mloc[j] = fmaxf(mloc[j], sv);
                    }
#pragma unroll
            for (int j = 0; j < 4; j++) {
                mloc[j] = fmaxf(mloc[j], __shfl_xor_sync(0xffffffffu, mloc[j], 4));
                mloc[j] = fmaxf(mloc[j], __shfl_xor_sync(0xffffffffu, mloc[j], 8));
                mloc[j] = fmaxf(mloc[j], __shfl_xor_sync(0xffffffffu, mloc[j], 16));
            }
            float corr[4];
#pragma unroll
            for (int j = 0; j < 4; j++) {
                const float newm = fmaxf(rm[j], mloc[j]);
                corr[j] = __expf(rm[j] - newm);
                rm[j] = newm;
            }
            float psum[4] = {0.f, 0.f, 0.f, 0.f};
#pragma unroll
            for (int mf = 0; mf < 4; mf++)
#pragma unroll
                for (int nf = 0; nf < 2; nf++)
#pragma unroll
                    for (int ci = 0; ci < 4; ci++) {
                        const int j = nf * 2 + (ci & 1);
                        const float p = __expf(sacc[mf][nf][ci] - rm[j]);
                        psum[j] += p;
                        const int key = mf * 16 + gid + ((ci >> 1) << 3);
                        const int qq  = nf * 8 + 2 * qid + (ci & 1);
                        Pw[qq * PROW + key] = __float2half(p);
                    }
#pragma unroll
            for (int j = 0; j < 4; j++) {
                psum[j] += __shfl_xor_sync(0xffffffffu, psum[j], 4);
                psum[j] += __shfl_xor_sync(0xffffffffu, psum[j], 8);
                psum[j] += __shfl_xor_sync(0xffffffffu, psum[j], 16);
                rl[j] = rl[j] * corr[j] + psum[j];
            }
#pragma unroll
            for (int mfo = 0; mfo < 8; mfo++)
#pragma unroll
                for (int nf = 0; nf < 2; nf++)
#pragma unroll
                    for (int ci = 0; ci < 4; ci++)
                        oacc[mfo][nf][ci] *= corr[nf * 2 + (ci & 1)];

            __syncwarp();

            // O^T += V^T @ P
#pragma unroll
            for (int ko = 0; ko < 4; ko++) {
                const int kcb = ko * 32 + lcol;
                uint32_t bp[2][2];
                {
                    uint32_t tp[4];
                    ldsm_x4(tp, pw_b + lrow * 144 + kcb);
                    bp[0][0] = tp[0]; bp[0][1] = tp[2];
                    bp[1][0] = tp[1]; bp[1][1] = tp[3];
                }
#pragma unroll
                for (int mfo = 0; mfo < 8; mfo++) {
                    uint32_t a[4];
                    ldsm_x4(a, vd + (mfo * 16 + lrow) * 144 + kcb);
#pragma unroll
                    for (int nf = 0; nf < 2; nf++)
                        mma_f16(oacc[mfo][nf], a, bp[nf]);
                }
            }
        }
    }

    float inv[4];
#pragma unroll
    for (int j = 0; j < 4; j++) inv[j] = 1.f / rl[j];
#pragma unroll
    for (int mfo = 0; mfo < 8; mfo++)
#pragma unroll
        for (int nf = 0; nf < 2; nf++)
#pragma unroll
            for (int ci = 0; ci < 4; ci++) {
                const int d = mfo * 16 + gid + ((ci >> 1) << 3);
                const int q = qb + q0 + nf * 8 + 2 * qid + (ci & 1);
                g_ctx[baseq + (size_t)q * DIM + d] =
                    __float2half(oacc[mfo][nf][ci] * inv[nf * 2 + (ci & 1)]);
            }
}

// ---------------------------------------------------------------------------
// Launch
// ---------------------------------------------------------------------------
extern "C" void kernel_launch(void* const* d_in, const int* in_sizes, int n_in,
                              void* d_out, int out_size)
{
    const float* x    = (const float*)d_in[0];
    const float* cosb = (const float*)d_in[2];
    const float* sinb = (const float*)d_in[3];
    const float* wq   = (const float*)d_in[5];
    const float* bq   = (const float*)d_in[6];
    const float* wk   = (const float*)d_in[7];
    const float* bk   = (const float*)d_in[8];
    const float* wv   = (const float*)d_in[9];
    const float* bv   = (const float*)d_in[10];
    const float* wo   = (const float*)d_in[11];
    const float* bo   = (const float*)d_in[12];
    float* out = (float*)d_out;

    __half *q, *k, *vt, *ctx, *cx, *cwq, *cwk, *cwv, *cwo;
    cudaGetSymbolAddress((void**)&q,   g_q);
    cudaGetSymbolAddress((void**)&k,   g_k);
    cudaGetSymbolAddress((void**)&vt,  g_vt);
    cudaGetSymbolAddress((void**)&ctx, g_ctx);
    cudaGetSymbolAddress((void**)&cx,  c_x);
    cudaGetSymbolAddress((void**)&cwq, c_wq);
    cudaGetSymbolAddress((void**)&cwk, c_wk);
    cudaGetSymbolAddress((void**)&cwv, c_wv);
    cudaGetSymbolAddress((void**)&cwo, c_wo);

    cudaFuncSetAttribute(attn_kernel,
                         cudaFuncAttributeMaxDynamicSharedMemorySize, SMEM_ATTN);
    cudaFuncSetAttribute(gemm_f16<1>,
                         cudaFuncAttributeMaxDynamicSharedMemorySize, SMEM_GEMM);
    cudaFuncSetAttribute(gemm_f16<0>,
                         cudaFuncAttributeMaxDynamicSharedMemorySize, SMEM_GEMM);

    // fp32 -> fp16 pre-conversion (fused, one launch)
    cvt5_kernel<<<(NCVT + 255) / 256, 256>>>(
        (const float4*)x, (const float4*)wq, (const float4*)wk,
        (const float4*)wv, (const float4*)wo,
        (__half2*)cx, (__half2*)cwq, (__half2*)cwk, (__half2*)cwv, (__half2*)cwo);

    // Fused QKV projections (+bias, +RoPE for q/k; v stored transposed)
    dim3 gqkv(DIM / 128, M / 128, 3);   // (16, 32, 3)
    gemm_f16<1><<<gqkv, 256, SMEM_GEMM>>>(cx, cwq, cwk, cwv, bq, bk, bv,
                                          q, k, vt, cosb, sinb);

    dim3 adim(S / 128, H, B);           // (8, 16, 4)
    attn_kernel<<<adim, 256, SMEM_ATTN>>>();

    dim3 gdim(DIM / 128, M / 128, 1);
    gemm_f16<0><<<gdim, 256, SMEM_GEMM>>>(ctx, cwo, cwo, cwo, bo, bo, bo,
                                          out, out, out, cosb, sinb);
}

// round 14
// speedup vs baseline: 1.0334x; 1.0121x over previous
#include <cuda_runtime.h>
#include <cuda_fp16.h>
#include <math.h>
#include <stdint.h>

// Problem constants
constexpr int B   = 4;
constexpr int S   = 1024;
constexpr int DIM = 2048;
constexpr int H   = 16;
constexpr int HD  = 128;
constexpr int M   = B * S;          // 4096 rows
constexpr float SCALE = 0.08838834764831845f;  // 1/sqrt(128)

// Scratch (allocation-free rule: __device__ globals), fp16.
__device__ __half g_q  [(size_t)M * DIM];
__device__ __half g_k  [(size_t)M * DIM];
__device__ __half g_vt [(size_t)M * DIM];   // transposed: [(b*H+h)*HD+d][s]
__device__ __half g_ctx[(size_t)M * DIM];
__device__ __half c_x  [(size_t)M * DIM];
__device__ __half c_wq [(size_t)DIM * DIM];
__device__ __half c_wk [(size_t)DIM * DIM];
__device__ __half c_wv [(size_t)DIM * DIM];
__device__ __half c_wo [(size_t)DIM * DIM];

__device__ __forceinline__ void mma_f16(float* c, const uint32_t* a, const uint32_t* b) {
    asm volatile(
        "mma.sync.aligned.m16n8k16.row.col.f32.f16.f16.f32 "
        "{%0,%1,%2,%3}, {%4,%5,%6,%7}, {%8,%9}, {%0,%1,%2,%3};"
        : "+f"(c[0]), "+f"(c[1]), "+f"(c[2]), "+f"(c[3])
        : "r"(a[0]), "r"(a[1]), "r"(a[2]), "r"(a[3]), "r"(b[0]), "r"(b[1]));
}

__device__ __forceinline__ void cp16(uint32_t dst, const void* src) {
    asm volatile("cp.async.cg.shared.global [%0], [%1], 16;" :: "r"(dst), "l"(src));
}

// ---------------------------------------------------------------------------
// Fused elementwise fp32 -> fp16 conversion for all 5 tensors.
// ---------------------------------------------------------------------------
constexpr int NX4 = M * DIM / 4;       // 2097152
constexpr int NW4 = DIM * DIM / 4;     // 1048576
constexpr int NCVT = NX4 + 4 * NW4;    // 6291456

__global__ void cvt5_kernel(const float4* __restrict__ x,
                            const float4* __restrict__ w0, const float4* __restrict__ w1,
                            const float4* __restrict__ w2, const float4* __restrict__ w3,
                            __half2* __restrict__ ox,
                            __half2* __restrict__ o0, __half2* __restrict__ o1,
                            __half2* __restrict__ o2, __half2* __restrict__ o3)
{
    const int i = blockIdx.x * blockDim.x + threadIdx.x;
    if (i >= NCVT) return;
    const float4* src; __half2* dst; int o;
    if (i < NX4) { src = x; dst = ox; o = i; }
    else {
        const int j = i - NX4;
        const int w = j >> 20;            // / NW4
        o = j & (NW4 - 1);
        src = (w == 0) ? w0 : (w == 1) ? w1 : (w == 2) ? w2 : w3;
        dst = (w == 0) ? o0 : (w == 1) ? o1 : (w == 2) ? o2 : o3;
    }
    float4 v = src[o];
    dst[2 * o]     = __floats2half2_rn(v.x, v.y);
    dst[2 * o + 1] = __floats2half2_rn(v.z, v.w);
}

// ---------------------------------------------------------------------------
// fp16 tensor-core GEMM (R7-winning config): 128x128 tile, BK=64,
// 2-stage cp.async, scalar fragment loads, m16n8k16, 8 warps (2x4).
// ---------------------------------------------------------------------------
constexpr int GROW   = 72;                   // halfs per padded row (144 B)
constexpr int ASTAGE = 128 * GROW;           // halfs per array per stage
constexpr int SMEM_GEMM = 2 * 2 * ASTAGE * 2;  // 73728 B

template <int QKV>
__global__ __launch_bounds__(256, 2)
void gemm_f16(const __half* __restrict__ A,
              const __half* __restrict__ W0, const __half* __restrict__ W1,
              const __half* __restrict__ W2,
              const float* __restrict__ b0, const float* __restrict__ b1,
              const float* __restrict__ b2,
              void* __restrict__ C0, void* __restrict__ C1, void* __restrict__ C2,
              const float* __restrict__ cosb, const float* __restrict__ sinb)
{
    constexpr int K = DIM;
    extern __shared__ __half smh[];

    const int z = QKV ? blockIdx.z : 0;
    const __half* W   = (z == 0) ? W0 : (z == 1) ? W1 : W2;
    const float* bias = (z == 0) ? b0 : (z == 1) ? b1 : b2;
    void* C           = (z == 0) ? C0 : (z == 1) ? C1 : C2;
    const bool rope   = QKV && (z < 2);

    const int tid  = threadIdx.x;
    const int warp = tid >> 5, lane = tid & 31;
    const int gid  = lane >> 2, qid = lane & 3;
    const int wm   = warp >> 2, wn = warp & 3;
    const int bm   = blockIdx.y * 128, bn = blockIdx.x * 128;
    const uint32_t sbase = (uint32_t)__cvta_generic_to_shared(smh);

    float acc[4][4][4];
#pragma unroll
    for (int i = 0; i < 4; i++)
#pragma unroll
        for (int j = 0; j < 4; j++)
#pragma unroll
            for (int c = 0; c < 4; c++) acc[i][j][c] = 0.f;

    auto prefetch = [&](int k0, int st) {
        const uint32_t ab = sbase + st * 2 * ASTAGE * 2;
        const uint32_t bb = ab + ASTAGE * 2;
#pragma unroll
        for (int i = 0; i < 4; i++) {
            const int c = tid + i * 256;        // 0..1023
            const int row = c >> 3, ch = c & 7; // 128 rows x 8 chunks (16B)
            cp16(ab + row * 144 + ch * 16, A + (size_t)(bm + row) * K + k0 + ch * 8);
            cp16(bb + row * 144 + ch * 16, W + (size_t)(bn + row) * K + k0 + ch * 8);
        }
        asm volatile("cp.async.commit_group;");
    };

    prefetch(0, 0);
    for (int slab = 0; slab < K / 64; slab++) {
        const int st = slab & 1;
        if (slab + 1 < K / 64) {
            prefetch(slab * 64 + 64, st ^ 1);
            asm volatile("cp.async.wait_group 1;" ::: "memory");
        } else {
            asm volatile("cp.async.wait_group 0;" ::: "memory");
        }
        __syncthreads();

        const uint32_t* As32 = (const uint32_t*)(smh + st * 2 * ASTAGE);
        const uint32_t* Bs32 = As32 + ASTAGE / 2;
#pragma unroll
        for (int ks = 0; ks < 4; ks++) {
            const int kw = ks * 8 + qid;
            uint32_t a[4][4], b[4][2];
#pragma unroll
            for (int mf = 0; mf < 4; mf++) {
                const int r = wm * 64 + mf * 16 + gid;
                a[mf][0] = As32[(r    ) * 36 + kw];
                a[mf][1] = As32[(r + 8) * 36 + kw];
                a[mf][2] = As32[(r    ) * 36 + kw + 4];
                a[mf][3] = As32[(r + 8) * 36 + kw + 4];
            }
#pragma unroll
            for (int nf = 0; nf < 4; nf++) {
                const int r = wn * 32 + nf * 8 + gid;
                b[nf][0] = Bs32[r * 36 + kw];
                b[nf][1] = Bs32[r * 36 + kw + 4];
            }
#pragma unroll
            for (int mf = 0; mf < 4; mf++)
#pragma unroll
                for (int nf = 0; nf < 4; nf++)
                    mma_f16(acc[mf][nf], a[mf], b[nf]);
        }
        __syncthreads();
    }

    // Epilogue: bias (+ RoPE on adjacent column pairs).
#pragma unroll
    for (int mf = 0; mf < 4; mf++) {
#pragma unroll
        for (int hf = 0; hf < 2; hf++) {
            const int row = bm + wm * 64 + mf * 16 + gid + hf * 8;
            const int s   = row & (S - 1);
#pragma unroll
            for (int nf = 0; nf < 4; nf++) {
                const int col = bn + wn * 32 + nf * 8 + 2 * qid;
                float v0 = acc[mf][nf][hf * 2 + 0] + bias[col];
                float v1 = acc[mf][nf][hf * 2 + 1] + bias[col + 1];
                if (rope) {
                    const int f = (col & (HD - 1)) >> 1;
                    const float cc = cosb[s * 64 + f], ss = sinb[s * 64 + f];
                    const float o0 = v0 * cc - v1 * ss;
                    const float o1 = v0 * ss + v1 * cc;
                    v0 = o0; v1 = o1;
                }
                if (QKV) {
                    if (z == 2) {
                        // transposed store: v_t[(b*H+h)*HD+d][s]
                        const int bb2 = row >> 10, sp = row & 1023;
                        const int hh = col >> 7, dd = col & 127;
                        __half* vt = (__half*)C;
                        vt[((size_t)((bb2 * H + hh) * HD + dd)) * S + sp] =
                            __float2half(v0);
                        vt[((size_t)((bb2 * H + hh) * HD + dd + 1)) * S + sp] =
                            __float2half(v1);
                    } else {
                        *(__half2*)((__half*)C + (size_t)row * DIM + col) =
                            __floats2half2_rn(v0, v1);
                    }
                } else {
                    *(float2*)((float*)C + (size_t)row * DIM + col) =
                        make_float2(v0, v1);
                }
            }
        }
    }
}

// ---------------------------------------------------------------------------
// fp16 tensor-core flash attention, 64 q-rows per CTA (2 CTAs/SM).
// 8 warps x 8 q; 64-key tiles, 2-stage cp.async double buffer.
// S^T = K Q^T, then O^T = V^T P (V pre-transposed in gmem).
// ---------------------------------------------------------------------------
constexpr int QROW = 136, KROW = 136, VROW = 72, PROW = 72;   // halfs per row
constexpr int SMEM_ATTN =
    (64 * QROW + 2 * 64 * KROW + 2 * 128 * VROW + 8 * 8 * PROW) * 2;  // 98304

__global__ __launch_bounds__(256, 2)
void attn_kernel()
{
    extern __shared__ __half smh[];
    __half* Qs  = smh;                       // [64 q][136 d]
    __half* Ks0 = Qs + 64 * QROW;            // 2 x [64 k][136 d]
    __half* Vt0 = Ks0 + 2 * 64 * KROW;       // 2 x [128 d][72 k]
    __half* Pb  = Vt0 + 2 * 128 * VROW;      // 8 x [8 q][72 k]

    const int tid  = threadIdx.x;
    const int warp = tid >> 5, lane = tid & 31;
    const int gid  = lane >> 2, qid = lane & 3;
    const int qb   = blockIdx.x * 64;
    const int h    = blockIdx.y;
    const int b    = blockIdx.z;
    const size_t baseq = (size_t)b * S * DIM + (size_t)h * HD;
    const size_t basev = (size_t)((b * H + h) * HD) * S;
    const int q0 = warp * 8;
    __half* Pw = Pb + warp * 8 * PROW;

    auto cp_tile = [&](int kb, int buf) {
        const uint32_t kd = (uint32_t)__cvta_generic_to_shared(Ks0 + buf * 64 * KROW);
        const uint32_t vd = (uint32_t)__cvta_generic_to_shared(Vt0 + buf * 128 * VROW);
#pragma unroll
        for (int i = 0; i < 4; i++) {          // K: 64 rows x 16 chunks
            const int c = tid + i * 256;
            const int row = c >> 4, ch = c & 15;
            cp16(kd + row * 272 + ch * 16,
                 g_k + baseq + (size_t)(kb + row) * DIM + ch * 8);
        }
#pragma unroll
        for (int i = 0; i < 4; i++) {          // V^T: 128 rows x 8 chunks
            const int c = tid + i * 256;
            const int row = c >> 3, ch = c & 7;
            cp16(vd + row * 144 + ch * 16,
                 g_vt + basev + (size_t)row * S + kb + ch * 8);
        }
        asm volatile("cp.async.commit_group;");
    };

    const int nt = qb / 64 + 1;
    cp_tile(0, 0);
    for (int i = tid; i < 1024; i += 256) {    // Q: 64 rows x 16 chunks
        const int row = i >> 4, ch = i & 15;
        *(uint4*)(Qs + row * QROW + ch * 8) =
            *(const uint4*)(g_q + baseq + (size_t)(qb + row) * DIM + ch * 8);
    }

    // O^T accumulators: [d-frag 8][4]; per-thread q columns = 2
    float oacc[8][4];
#pragma unroll
    for (int i = 0; i < 8; i++)
#pragma unroll
        for (int c = 0; c < 4; c++) oacc[i][c] = 0.f;
    float rm[2] = {-1e30f, -1e30f};
    float rl[2] = {0.f, 0.f};

    const uint32_t* Q32 = (const uint32_t*)Qs;
    const uint32_t* P32 = (const uint32_t*)Pw;

    for (int t = 0; t < nt; t++) {
        const int kb = t * 64;
        const int buf = t & 1;
        if (t + 1 < nt) {
            cp_tile(kb + 64, buf ^ 1);
            asm volatile("cp.async.wait_group 1;" ::: "memory");
        } else {
            asm volatile("cp.async.wait_group 0;" ::: "memory");
        }
        __syncthreads();

        const uint32_t* K32 = (const uint32_t*)(Ks0 + buf * 64 * KROW);
        const uint32_t* V32 = (const uint32_t*)(Vt0 + buf * 128 * VROW);

        if (kb <= qb + q0 + 7) {
            // S^T = K @ Q^T : [64 key][8 q] per warp
            float sacc[4][4];
#pragma unroll
            for (int i = 0; i < 4; i++)
#pragma unroll
                for (int c = 0; c < 4; c++) sacc[i][c] = 0.f;

#pragma unroll
            for (int ks8 = 0; ks8 < 64; ks8 += 8) {   // 8 k-steps of 16
                const int kw = ks8 + qid;
                uint32_t a[4][4], bq[2];
#pragma unroll
                for (int mf = 0; mf < 4; mf++) {
                    const int r = mf * 16 + gid;
                    a[mf][0] = K32[(r    ) * 68 + kw];
                    a[mf][1] = K32[(r + 8) * 68 + kw];
                    a[mf][2] = K32[(r    ) * 68 + kw + 4];
                    a[mf][3] = K32[(r + 8) * 68 + kw + 4];
                }
                {
                    const int q = q0 + gid;
                    bq[0] = Q32[q * 68 + kw];
                    bq[1] = Q32[q * 68 + kw + 4];
                }
#pragma unroll
                for (int mf = 0; mf < 4; mf++)
                    mma_f16(sacc[mf], a[mf], bq);
            }

            const bool diag = (kb + 63 > qb + q0);
            float mloc[2] = {-1e30f, -1e30f};
#pragma unroll
            for (int mf = 0; mf < 4; mf++)
#pragma unroll
                for (int ci = 0; ci < 4; ci++) {
                    float sv = sacc[mf][ci] * SCALE;
                    if (diag) {
                        const int key = kb + mf * 16 + gid + ((ci >> 1) << 3);
                        const int q   = qb + q0 + 2 * qid + (ci & 1);
                        if (key > q) sv = -1e30f;
                    }
                    sacc[mf][ci] = sv;
                    mloc[ci & 1] = fmaxf(mloc[ci & 1], sv);
                }
#pragma unroll
            for (int j = 0; j < 2; j++) {
                mloc[j] = fmaxf(mloc[j], __shfl_xor_sync(0xffffffffu, mloc[j], 4));
                mloc[j] = fmaxf(mloc[j], __shfl_xor_sync(0xffffffffu, mloc[j], 8));
                mloc[j] = fmaxf(mloc[j], __shfl_xor_sync(0xffffffffu, mloc[j], 16));
            }
            float corr[2];
#pragma unroll
            for (int j = 0; j < 2; j++) {
                const float newm = fmaxf(rm[j], mloc[j]);
                corr[j] = __expf(rm[j] - newm);
                rm[j] = newm;
            }
            float psum[2] = {0.f, 0.f};
#pragma unroll
            for (int mf = 0; mf < 4; mf++)
#pragma unroll
                for (int ci = 0; ci < 4; ci++) {
                    const int j = ci & 1;
                    const float p = __expf(sacc[mf][ci] - rm[j]);
                    psum[j] += p;
                    const int key = mf * 16 + gid + ((ci >> 1) << 3);
                    const int qq  = 2 * qid + (ci & 1);
                    Pw[qq * PROW + key] = __float2half(p);
                }
#pragma unroll
            for (int j = 0; j < 2; j++) {
                psum[j] += __shfl_xor_sync(0xffffffffu, psum[j], 4);
                psum[j] += __shfl_xor_sync(0xffffffffu, psum[j], 8);
                psum[j] += __shfl_xor_sync(0xffffffffu, psum[j], 16);
                rl[j] = rl[j] * corr[j] + psum[j];
            }
#pragma unroll
            for (int mfo = 0; mfo < 8; mfo++)
#pragma unroll
                for (int ci = 0; ci < 4; ci++)
                    oacc[mfo][ci] *= corr[ci & 1];

            __syncwarp();

            // O^T += V^T @ P
#pragma unroll
            for (int ko = 0; ko < 4; ko++) {
                const int kw = ko * 8 + qid;
                uint32_t bp[2];
                {
                    const int q = gid;
                    bp[0] = P32[q * 36 + kw];
                    bp[1] = P32[q * 36 + kw + 4];
                }
#pragma unroll
                for (int mfo = 0; mfo < 8; mfo++) {
                    const int d = mfo * 16 + gid;
                    uint32_t a[4];
                    a[0] = V32[(d    ) * 36 + kw];
                    a[1] = V32[(d + 8) * 36 + kw];
                    a[2] = V32[(d    ) * 36 + kw + 4];
                    a[3] = V32[(d + 8) * 36 + kw + 4];
                    mma_f16(oacc[mfo], a, bp);
                }
            }
        }
        __syncthreads();
    }

    float inv[2];
#pragma unroll
    for (int j = 0; j < 2; j++) inv[j] = 1.f / rl[j];
#pragma unroll
    for (int mfo = 0; mfo < 8; mfo++)
#pragma unroll
        for (int ci = 0; ci < 4; ci++) {
            const int d = mfo * 16 + gid + ((ci >> 1) << 3);
            const int q = qb + q0 + 2 * qid + (ci & 1);
            g_ctx[baseq + (size_t)q * DIM + d] =
                __float2half(oacc[mfo][ci] * inv[ci & 1]);
        }
}

// ---------------------------------------------------------------------------
// Launch
// ---------------------------------------------------------------------------
extern "C" void kernel_launch(void* const* d_in, const int* in_sizes, int n_in,
                              void* d_out, int out_size)
{
    const float* x    = (const float*)d_in[0];
    const float* cosb = (const float*)d_in[2];
    const float* sinb = (const float*)d_in[3];
    const float* wq   = (const float*)d_in[5];
    const float* bq   = (const float*)d_in[6];
    const float* wk   = (const float*)d_in[7];
    const float* bk   = (const float*)d_in[8];
    const float* wv   = (const float*)d_in[9];
    const float* bv   = (const float*)d_in[10];
    const float* wo   = (const float*)d_in[11];
    const float* bo   = (const float*)d_in[12];
    float* out = (float*)d_out;

    __half *q, *k, *vt, *ctx, *cx, *cwq, *cwk, *cwv, *cwo;
    cudaGetSymbolAddress((void**)&q,   g_q);
    cudaGetSymbolAddress((void**)&k,   g_k);
    cudaGetSymbolAddress((void**)&vt,  g_vt);
    cudaGetSymbolAddress((void**)&ctx, g_ctx);
    cudaGetSymbolAddress((void**)&cx,  c_x);
    cudaGetSymbolAddress((void**)&cwq, c_wq);
    cudaGetSymbolAddress((void**)&cwk, c_wk);
    cudaGetSymbolAddress((void**)&cwv, c_wv);
    cudaGetSymbolAddress((void**)&cwo, c_wo);

    cudaFuncSetAttribute(attn_kernel,
                         cudaFuncAttributeMaxDynamicSharedMemorySize, SMEM_ATTN);
    cudaFuncSetAttribute(gemm_f16<1>,
                         cudaFuncAttributeMaxDynamicSharedMemorySize, SMEM_GEMM);
    cudaFuncSetAttribute(gemm_f16<0>,
                         cudaFuncAttributeMaxDynamicSharedMemorySize, SMEM_GEMM);

    // fp32 -> fp16 pre-conversion (fused, one launch)
    cvt5_kernel<<<(NCVT + 255) / 256, 256>>>(
        (const float4*)x, (const float4*)wq, (const float4*)wk,
        (const float4*)wv, (const float4*)wo,
        (__half2*)cx, (__half2*)cwq, (__half2*)cwk, (__half2*)cwv, (__half2*)cwo);

    // Fused QKV projections (+bias, +RoPE for q/k; v stored transposed)
    dim3 gqkv(DIM / 128, M / 128, 3);   // (16, 32, 3)
    gemm_f16<1><<<gqkv, 256, SMEM_GEMM>>>(cx, cwq, cwk, cwv, bq, bk, bv,
                                          q, k, vt, cosb, sinb);

    dim3 adim(S / 64, H, B);            // (16, 16, 4)
    attn_kernel<<<adim, 256, SMEM_ATTN>>>();

    dim3 gdim(DIM / 128, M / 128, 1);
    gemm_f16<0><<<gdim, 256, SMEM_GEMM>>>(ctx, cwo, cwo, cwo, bo, bo, bo,
                                          out, out, out, cosb, sinb);
}